// round 12
// baseline (speedup 1.0000x reference)
#include <cuda_runtime.h>
#include <math.h>
#include <cstdint>

// Shapes (fixed by dataset):
//   features: [B=2, C=512, H=50, W=64] float32
//   roiss   : [B=2, N=128, 4]          float32
//   out     : [B, N, C]                float32
#define BB 2
#define CC 512
#define HH 50
#define WW 64
#define NN 128
#define HWSZ (HH * WW)        // 3200
#define PLANE_BYTES (HWSZ * 4) // 12800, multiple of 16

// ---------------------------------------------------------------------------
// TMA-staged plane ROI max-pool.
//   grid = B*C = 1024 blocks; block = 256 (8 warps).
//   Phase 1: ONE cp.async.bulk (TMA) copies the 12.8 KB (b,c) plane to smem
//            (hardware-managed MLP — fixes the MLP=1 LDG->STS staging of R11).
//   Phase 2 (overlapped with the copy): threads 0..127 compute the 128 boxes.
//            x-path: rn(rn(x/1024)*64) is exact power-of-2 scaling == x*0.0625f
//            (bit-identical); y-path keeps the IEEE divide.
//   Phase 3: warp answers 8 ROIs x 4 float2 chunks, 2 passes (128 ROIs/block);
//            8-deep predicated row unroll, column mask once, 2x shfl_xor.
// Global traffic: exactly 13.1 MB, streamed by TMA.
// ---------------------------------------------------------------------------
__global__ __launch_bounds__(256, 8) void roipool_tma_kernel(
    const float* __restrict__ feat,
    const float* __restrict__ rois,
    float* __restrict__ out)
{
    __shared__ __align__(16) float plane[HWSZ];
    __shared__ int4 sbox[NN];                       // x1, xe, y1, ye
    __shared__ __align__(8) unsigned long long mbar;

    const int b   = blockIdx.x >> 9;                // 0..1
    const int c   = blockIdx.x & 511;               // 0..511
    const int tid = threadIdx.x;

    const uint32_t mbar_a  = (uint32_t)__cvta_generic_to_shared(&mbar);
    const uint32_t plane_a = (uint32_t)__cvta_generic_to_shared(plane);

    if (tid == 0)
        asm volatile("mbarrier.init.shared.b64 [%0], 1;" :: "r"(mbar_a));
    __syncthreads();   // init visible to all waiters before any poll

    if (tid == 0) {
        asm volatile("mbarrier.arrive.expect_tx.shared.b64 _, [%0], %1;"
                     :: "r"(mbar_a), "r"((uint32_t)PLANE_BYTES));
        const float* src = feat + (size_t)(b * CC + c) * HWSZ;
        asm volatile(
            "cp.async.bulk.shared::cta.global.mbarrier::complete_tx::bytes "
            "[%0], [%1], %2, [%3];"
            :: "r"(plane_a), "l"(src), "r"((uint32_t)PLANE_BYTES), "r"(mbar_a)
            : "memory");
    }

    // ---- Phase 2 (overlaps the TMA fill): boxes, byte-identical ints ----
    if (tid < NN) {
        const float4 r = reinterpret_cast<const float4*>(rois)[b * NN + tid];
        const float nx1 = __fmul_rn(r.x, 0.0625f);  // == rn(rn(x/1024)*64)
        const float nx2 = __fmul_rn(r.z, 0.0625f);  // (exact pow2 scaling)
        const float ny1 = __fmul_rn(__fdiv_rn(r.y, 800.0f), (float)HH);
        const float ny2 = __fmul_rn(__fdiv_rn(r.w, 800.0f), (float)HH);

        int x1 = max((int)floorf(nx1), 0);
        int y1 = max((int)floorf(ny1), 0);
        int x2 = max((int)ceilf(nx2), 0);
        int y2 = max((int)ceilf(ny2), 0);

        if (x1 == 0 && x2 == 0) x2 = 1;
        if (y1 == 0 && y2 == 0) y2 = 1;
        if (x1 >= WW) x1 = WW - 1;
        if (y1 >= HH) y1 = HH - 1;

        sbox[tid] = make_int4(x1, min(x2, WW), y1, min(y2, HH));
    }

    // ---- Wait for the plane (acquire orders the TMA data) ----
    {
        uint32_t done;
        asm volatile(
            "{\n\t.reg .pred p;\n\t"
            "mbarrier.try_wait.parity.acquire.cta.shared::cta.b64 p, [%1], %2;\n\t"
            "selp.b32 %0, 1, 0, p;\n\t}"
            : "=r"(done) : "r"(mbar_a), "r"(0u) : "memory");
        while (!done) {
            asm volatile(
                "{\n\t.reg .pred p;\n\t"
                "mbarrier.try_wait.parity.acquire.cta.shared::cta.b64 p, [%1], %2, 0x989680;\n\t"
                "selp.b32 %0, 1, 0, p;\n\t}"
                : "=r"(done) : "r"(mbar_a), "r"(0u) : "memory");
        }
    }
    __syncthreads();   // also publishes sbox to all warps

    // ---- Phase 3: answer ROIs from smem ----
    const int w     = tid >> 5;         // warp 0..7
    const int lane  = tid & 31;
    const int rsub  = lane >> 2;        // 0..7 roi slot within warp
    const int chunk = lane & 3;         // 0..3 float2 chunk

    #pragma unroll
    for (int pass = 0; pass < 2; ++pass) {
        const int n = w * 16 + pass * 8 + rsub;
        const int4 bx = sbox[n];
        const int x1 = bx.x, xe = bx.y, y1 = bx.z, ye = bx.w;
        const int hgt = ye - y1;                    // <= 7 here
        const int xa  = x1 & ~1;                    // 8B-aligned span start
        const int xb  = xa + chunk * 2;
        const bool ok = (xb < xe);

        float m0 = -INFINITY, m1 = -INFINITY;

        #pragma unroll
        for (int j = 0; j < 8; ++j) {
            if (ok && j < hgt) {
                const float2 v = *reinterpret_cast<const float2*>(
                    &plane[(y1 + j) * WW + xb]);
                m0 = fmaxf(m0, v.x);
                m1 = fmaxf(m1, v.y);
            }
        }
        // safety tails (never taken with these shapes)
        for (int j = 8; j < hgt; ++j) {
            if (ok) {
                const float2 v = *reinterpret_cast<const float2*>(
                    &plane[(y1 + j) * WW + xb]);
                m0 = fmaxf(m0, v.x);
                m1 = fmaxf(m1, v.y);
            }
        }
        for (int xx = xa + 8 + chunk; xx < xe; xx += 4)
            for (int j = 0; j < hgt; ++j)
                m0 = fmaxf(m0, plane[(y1 + j) * WW + xx]);

        const float v0 = (xb + 0 >= x1 && xb + 0 < xe) ? m0 : -INFINITY;
        const float v1 = (xb + 1 >= x1 && xb + 1 < xe) ? m1 : -INFINITY;
        float v = fmaxf(v0, v1);

        v = fmaxf(v, __shfl_xor_sync(0xFFFFFFFFu, v, 1));
        v = fmaxf(v, __shfl_xor_sync(0xFFFFFFFFu, v, 2));

        if (chunk == 0)
            out[(size_t)(b * NN + n) * CC + c] = v;
    }
}

extern "C" void kernel_launch(void* const* d_in, const int* in_sizes, int n_in,
                              void* d_out, int out_size)
{
    const float* feat = (const float*)d_in[0];   // [B, C, H, W]
    const float* rois = (const float*)d_in[1];   // [B, N, 4]
    float* out        = (float*)d_out;           // [B, N, C]
    (void)in_sizes; (void)n_in; (void)out_size;

    roipool_tma_kernel<<<BB * CC, 256>>>(feat, rois, out);
}